// round 5
// baseline (speedup 1.0000x reference)
#include <cuda_runtime.h>
#include <cuda_fp16.h>
#include <mma.h>

using namespace nvcuda;

#define HDIM 7168
#define NEXP 256
#define TOPK 8
#define SCALE_F 2.5f
#define MAX_T 8192
#define TAU_E 2e-5f
#define TAU_G 4e-5f
#define TPG 4

#define BM 128
#define BN 128
#define BK 32
#define NIT (HDIM / BK)      // 224
#define LDH 40               // smem stride in halves (mult of 8 -> 16B rows)
#define AR (128 * LDH)       // halves per smem matrix (5120)
#define GEMM_SMEM (8 * AR * 2)   // 81920 bytes (2 stages x {Ahi,Alo,Bhi,Blo})

__device__ __half g_Whi[NEXP * HDIM];
__device__ __half g_Wlo[NEXP * HDIM];
__device__ float  g_scores[MAX_T * NEXP];
__device__ int    g_nflag;
__device__ int    g_flags[MAX_T];

typedef unsigned long long ull;

// ---- packed f32x2 helpers (exact repair path) ----
__device__ __forceinline__ ull pack2(float lo, float hi) {
    ull r; asm("mov.b64 %0, {%1, %2};" : "=l"(r) : "f"(lo), "f"(hi)); return r;
}
__device__ __forceinline__ void fma2_acc(ull& acc, ull a, ull b) {
    asm("fma.rn.f32x2 %0, %1, %2, %0;" : "+l"(acc) : "l"(a), "l"(b));
}
__device__ __forceinline__ ull fma2(ull a, ull b, ull c) {
    ull d; asm("fma.rn.f32x2 %0, %1, %2, %3;" : "=l"(d) : "l"(a), "l"(b), "l"(c)); return d;
}
__device__ __forceinline__ ull add2(ull a, ull b) {
    ull d; asm("add.rn.f32x2 %0, %1, %2;" : "=l"(d) : "l"(a), "l"(b)); return d;
}
__device__ __forceinline__ float2 unpk2(ull v) {
    float lo, hi; asm("mov.b64 {%0, %1}, %2;" : "=f"(lo), "=f"(hi) : "l"(v));
    return make_float2(lo, hi);
}

// ---------- K1: split W (x256) into fp16 hi/lo; reset flag counter ----------
__global__ void prep_kernel(const float* __restrict__ W) {
    if (blockIdx.x == 0 && threadIdx.x == 0) g_nflag = 0;
    const int total = NEXP * HDIM;
    for (int i = blockIdx.x * blockDim.x + threadIdx.x; i < total;
         i += gridDim.x * blockDim.x) {
        float ws = W[i] * 256.0f;
        __half h = __float2half_rn(ws);
        g_Whi[i] = h;
        g_Wlo[i] = __float2half_rn(ws - __half2float(h));
    }
}

// ---------- K2: wmma fp16 split-2 GEMM + bias + sigmoid -> g_scores ----------
__global__ __launch_bounds__(256, 1)
void gemm_kernel(const float* __restrict__ X, const float* __restrict__ bvec, int T)
{
    extern __shared__ __half sh[];
    const int tid = threadIdx.x;
    const int wid = tid >> 5;
    const int n0 = blockIdx.x * BN;
    const int m0 = blockIdx.y * BM;
    const int wm = wid & 3;          // 4 m-warps (32 rows each)
    const int wn = wid >> 2;         // 2 n-warps (64 cols each)

    // global prefetch mappings
    const int a_row = tid >> 3, a_c4 = tid & 7;       // + 256*i, i<4
    const int b_row = tid >> 2, b_p  = tid & 3;       // + 256*i, i<2

    wmma::fragment<wmma::accumulator, 16, 16, 16, float> acc[2][4];
#pragma unroll
    for (int mt = 0; mt < 2; ++mt)
#pragma unroll
        for (int nt = 0; nt < 4; ++nt) wmma::fill_fragment(acc[mt][nt], 0.0f);

    float4 av[4];
    uint4 bh[2], bl[2];

    auto fill = [&](int stage) {
        __half* Ahi = sh + stage * 4 * AR;
        __half* Alo = Ahi + AR;
        __half* Bhi = Alo + AR;
        __half* Blo = Bhi + AR;
#pragma unroll
        for (int i = 0; i < 4; ++i) {
            const int idx = tid + 256 * i;
            const int row = idx >> 3, c4 = idx & 7;
            float4 v = av[i];
            __half2 h01 = __floats2half2_rn(v.x, v.y);
            __half2 h23 = __floats2half2_rn(v.z, v.w);
            float2 f01 = __half22float2(h01), f23 = __half22float2(h23);
            __half2 l01 = __floats2half2_rn(v.x - f01.x, v.y - f01.y);
            __half2 l23 = __floats2half2_rn(v.z - f23.x, v.w - f23.y);
            uint2 ph, pl;
            ph.x = reinterpret_cast<unsigned&>(h01); ph.y = reinterpret_cast<unsigned&>(h23);
            pl.x = reinterpret_cast<unsigned&>(l01); pl.y = reinterpret_cast<unsigned&>(l23);
            *(uint2*)(Ahi + row * LDH + c4 * 4) = ph;
            *(uint2*)(Alo + row * LDH + c4 * 4) = pl;
        }
#pragma unroll
        for (int i = 0; i < 2; ++i) {
            const int idx = tid + 256 * i;
            const int row = idx >> 2, p = idx & 3;
            *(uint4*)(Bhi + row * LDH + p * 8) = bh[i];
            *(uint4*)(Blo + row * LDH + p * 8) = bl[i];
        }
    };

    auto gload = [&](int it) {
        const int kc = it * BK;
#pragma unroll
        for (int i = 0; i < 4; ++i) {
            const int idx = tid + 256 * i;
            const int row = idx >> 3, c4 = idx & 7;
            av[i] = __ldg((const float4*)(X + (size_t)(m0 + row) * HDIM + kc + c4 * 4));
        }
#pragma unroll
        for (int i = 0; i < 2; ++i) {
            const int idx = tid + 256 * i;
            const int row = idx >> 2, p = idx & 3;
            bh[i] = __ldg((const uint4*)(g_Whi + (size_t)(n0 + row) * HDIM + kc) + p);
            bl[i] = __ldg((const uint4*)(g_Wlo + (size_t)(n0 + row) * HDIM + kc) + p);
        }
    };

    gload(0);
    fill(0);
    __syncthreads();

    for (int it = 0; it < NIT; ++it) {
        const int buf = it & 1;
        const bool has_next = (it + 1) < NIT;
        if (has_next) gload(it + 1);

        const __half* Ahi = sh + buf * 4 * AR;
        const __half* Alo = Ahi + AR;
        const __half* Bhi = Alo + AR;
        const __half* Blo = Bhi + AR;
#pragma unroll
        for (int kk = 0; kk < 2; ++kk) {
            wmma::fragment<wmma::matrix_a, 16, 16, 16, __half, wmma::row_major> ah[2], al[2];
#pragma unroll
            for (int mt = 0; mt < 2; ++mt) {
                const int r = wm * 32 + mt * 16;
                wmma::load_matrix_sync(ah[mt], Ahi + r * LDH + kk * 16, LDH);
                wmma::load_matrix_sync(al[mt], Alo + r * LDH + kk * 16, LDH);
            }
#pragma unroll
            for (int nt = 0; nt < 4; ++nt) {
                const int c = wn * 64 + nt * 16;
                wmma::fragment<wmma::matrix_b, 16, 16, 16, __half, wmma::col_major> fbh, fbl;
                wmma::load_matrix_sync(fbh, Bhi + c * LDH + kk * 16, LDH);
                wmma::load_matrix_sync(fbl, Blo + c * LDH + kk * 16, LDH);
#pragma unroll
                for (int mt = 0; mt < 2; ++mt) {
                    wmma::mma_sync(acc[mt][nt], ah[mt], fbh, acc[mt][nt]);
                    wmma::mma_sync(acc[mt][nt], ah[mt], fbl, acc[mt][nt]);
                    wmma::mma_sync(acc[mt][nt], al[mt], fbh, acc[mt][nt]);
                }
            }
        }
        __syncthreads();
        if (has_next) {
            fill(buf ^ 1);
            __syncthreads();
        }
    }

    // epilogue: stage acc in smem, then bias+sigmoid -> g_scores
    float* sacc = (float*)sh;     // 128x128 fp32 = 64KB
#pragma unroll
    for (int mt = 0; mt < 2; ++mt)
#pragma unroll
        for (int nt = 0; nt < 4; ++nt)
            wmma::store_matrix_sync(sacc + (wm * 32 + mt * 16) * 128 + wn * 64 + nt * 16,
                                    acc[mt][nt], 128, wmma::mem_row_major);
    __syncthreads();
#pragma unroll
    for (int i = 0; i < 16; ++i) {
        const int idx = tid + 256 * i;
        const int row = idx >> 5, c4 = idx & 31;
        float4 v = *(float4*)(sacc + row * 128 + c4 * 4);
        const int n = n0 + c4 * 4;
        float4 o;
        o.x = 1.0f / (1.0f + expf(-(v.x * (1.0f/256.0f) + bvec[n])));
        o.y = 1.0f / (1.0f + expf(-(v.y * (1.0f/256.0f) + bvec[n+1])));
        o.z = 1.0f / (1.0f + expf(-(v.z * (1.0f/256.0f) + bvec[n+2])));
        o.w = 1.0f / (1.0f + expf(-(v.w * (1.0f/256.0f) + bvec[n+3])));
        *(float4*)(g_scores + (size_t)(m0 + row) * NEXP + n) = o;
    }
}

// ---------- warp-collective routing core ----------
__device__ __forceinline__ void route_token(const float* __restrict__ rs,
                                            const float* __restrict__ ebias,
                                            int lane, int t, int T,
                                            float* __restrict__ out, bool check)
{
    const float NEG_INF = -1e30f;
    float sfc[8];
#pragma unroll
    for (int i = 0; i < 8; ++i) sfc[i] = rs[i * 32 + lane] + ebias[i * 32 + lane];

    float gs[8];
#pragma unroll
    for (int i = 0; i < 8; ++i) {
        float m1 = sfc[i], m2 = NEG_INF;
#pragma unroll
        for (int off = 16; off > 0; off >>= 1) {
            float o1 = __shfl_xor_sync(0xffffffffu, m1, off);
            float o2 = __shfl_xor_sync(0xffffffffu, m2, off);
            float hi = fmaxf(m1, o1), lo = fminf(m1, o1);
            m1 = hi; m2 = fmaxf(fmaxf(m2, o2), lo);
        }
        gs[i] = m1 + m2;
    }

    unsigned gmask = 0, sel = 0;
    float g4 = 0.0f, g5 = 0.0f;
#pragma unroll
    for (int j = 0; j < 5; ++j) {
        float best = NEG_INF; int bg = 0;
#pragma unroll
        for (int g = 0; g < 8; ++g)
            if (!((sel >> g) & 1u) && gs[g] > best) { best = gs[g]; bg = g; }
        sel |= (1u << bg);
        if (j < 4) gmask |= (1u << bg);
        if (j == 3) g4 = best;
        if (j == 4) g5 = best;
    }

    float cv[8];
#pragma unroll
    for (int i = 0; i < 8; ++i) cv[i] = ((gmask >> i) & 1u) ? sfc[i] : 0.0f;

    unsigned used = 0;
    int idxs[8];
    float mmin = 1e30f, pv = 0.0f;
#pragma unroll
    for (int j = 0; j < 9; ++j) {
        float bv = NEG_INF; int be = 1 << 30;
#pragma unroll
        for (int i = 0; i < 8; ++i) {
            if (!((used >> i) & 1u)) {
                const float v = cv[i];
                const int e = i * 32 + lane;
                if (v > bv || (v == bv && e < be)) { bv = v; be = e; }
            }
        }
#pragma unroll
        for (int off = 16; off > 0; off >>= 1) {
            float ov = __shfl_xor_sync(0xffffffffu, bv, off);
            int oe = __shfl_xor_sync(0xffffffffu, be, off);
            if (ov > bv || (ov == bv && oe < be)) { bv = ov; be = oe; }
        }
        if (j < 8) idxs[j] = be;
        if ((be & 31) == lane) used |= (1u << (be >> 5));
        if (j > 0) mmin = fminf(mmin, pv - bv);
        pv = bv;
    }

    if (check && (mmin < TAU_E || (g4 - g5) < TAU_G)) {
        if (lane == 0) { int s = atomicAdd(&g_nflag, 1); g_flags[s] = t; }
    }

    float wj = 0.0f;
    if (lane < TOPK) wj = rs[idxs[lane]];
    float ssum = wj;
#pragma unroll
    for (int off = 4; off > 0; off >>= 1)
        ssum += __shfl_xor_sync(0xffffffffu, ssum, off);
    const float denom = ssum + 1e-20f;
    if (lane < TOPK) {
        out[(size_t)t * TOPK + lane] = (float)idxs[lane];
        out[(size_t)T * TOPK + (size_t)t * TOPK + lane] = wj / denom * SCALE_F;
    }
}

// ---------- K3: router ----------
__global__ __launch_bounds__(128)
void router_kernel(const float* __restrict__ ebias, float* __restrict__ out, int T)
{
    __shared__ float raw_s[4][NEXP];
    const int warp = threadIdx.x >> 5;
    const int lane = threadIdx.x & 31;
    const int t = blockIdx.x * 4 + warp;
    if (t >= T) return;
    float* rs = raw_s[warp];
#pragma unroll
    for (int i = 0; i < 2; ++i)
        *(float4*)(rs + i * 128 + lane * 4) =
            *(const float4*)(g_scores + (size_t)t * NEXP + i * 128 + lane * 4);
    __syncwarp();
    route_token(rs, ebias, lane, t, T, out, true);
}

// ---------- K4: exact repair for flagged tokens ----------
__global__ __launch_bounds__(256)
void repair_kernel(const float* __restrict__ X, const float* __restrict__ W,
                   const float* __restrict__ bvec, const float* __restrict__ ebias,
                   float* __restrict__ out, int T)
{
    extern __shared__ float xs[];                  // TPG * HDIM floats
    __shared__ float sc[TPG][NEXP];
    __shared__ int toks[TPG];
    const int tid = threadIdx.x;
    const int warp = tid >> 5, lane = tid & 31;
    const ull neg1 = pack2(-1.0f, -1.0f);

    for (int g = blockIdx.x; g * TPG < g_nflag; g += gridDim.x) {
        const int base = g * TPG;
        const int nt = min(TPG, g_nflag - base);
        if (tid < TPG) toks[tid] = (tid < nt) ? g_flags[base + tid] : -1;
        __syncthreads();
        for (int j = 0; j < nt; ++j) {
            const float4* src = (const float4*)(X + (size_t)toks[j] * HDIM);
            float4* dstv = (float4*)(xs + j * HDIM);
            for (int i = tid; i < HDIM / 4; i += 256) dstv[i] = src[i];
        }
        __syncthreads();

        {
            const int e = tid;
            const float2* wrow = (const float2*)(W + (size_t)e * HDIM);
            ull alo[TPG], ahi[TPG], cmp[TPG];
#pragma unroll
            for (int j = 0; j < TPG; ++j) { alo[j] = 0; ahi[j] = 0; cmp[j] = 0; }
            for (int kk = 0; kk < HDIM / 2; kk += 16) {
#pragma unroll
                for (int u = 0; u < 16; ++u) {
                    float2 wv = __ldg(wrow + kk + u);
                    ull w2 = pack2(wv.x, wv.y);
#pragma unroll
                    for (int j = 0; j < TPG; ++j) {
                        float2 xv = *(const float2*)(xs + j * HDIM + 2 * (kk + u));
                        fma2_acc(alo[j], w2, pack2(xv.x, xv.y));
                    }
                }
#pragma unroll
                for (int j = 0; j < TPG; ++j) {
                    ull y = fma2(cmp[j], neg1, alo[j]);
                    ull tt = add2(ahi[j], y);
                    ull d = fma2(ahi[j], neg1, tt);
                    cmp[j] = fma2(y, neg1, d);
                    ahi[j] = tt;
                    alo[j] = 0;
                }
            }
#pragma unroll
            for (int j = 0; j < TPG; ++j) {
                float2 v = unpk2(fma2(cmp[j], neg1, ahi[j]));
                float l = v.x + v.y + bvec[e];
                sc[j][e] = 1.0f / (1.0f + expf(-l));
            }
        }
        __syncthreads();
        if (warp < nt) route_token(sc[warp], ebias, lane, toks[warp], T, out, false);
        __syncthreads();
    }
}

extern "C" void kernel_launch(void* const* d_in, const int* in_sizes, int n_in,
                              void* d_out, int out_size)
{
    const float* hs = (const float*)d_in[0];
    const float* W  = (const float*)d_in[1];
    const float* b  = (const float*)d_in[2];
    const float* eb = (const float*)d_in[3];
    const int T = in_sizes[0] / HDIM;

    cudaFuncSetAttribute(gemm_kernel, cudaFuncAttributeMaxDynamicSharedMemorySize, GEMM_SMEM);
    cudaFuncSetAttribute(repair_kernel, cudaFuncAttributeMaxDynamicSharedMemorySize,
                         TPG * HDIM * (int)sizeof(float));

    prep_kernel<<<256, 256>>>(W);
    dim3 ggrid(NEXP / BN, T / BM);
    gemm_kernel<<<ggrid, 256, GEMM_SMEM>>>(hs, b, T);
    router_kernel<<<(T + 3) / 4, 128>>>(eb, (float*)d_out, T);
    repair_kernel<<<64, 256, TPG * HDIM * (int)sizeof(float)>>>(hs, W, b, eb, (float*)d_out, T);
}

// round 6
// speedup vs baseline: 1.3941x; 1.3941x over previous
#include <cuda_runtime.h>
#include <cuda_fp16.h>
#include <mma.h>

using namespace nvcuda;

#define HDIM 7168
#define NEXP 256
#define TOPK 8
#define SCALE_F 2.5f
#define MAX_T 8192
#define TAU_E 2e-5f
#define TAU_G 4e-5f
#define TPG 8            // tokens per repair block (= warps)

#define BM 128
#define BN 128
#define BK 32
#define NIT (HDIM / BK)      // 224
#define LDH 40
#define AR (128 * LDH)
#define GEMM_SMEM (8 * AR * 2)

// repair smem: ws[2][256][33] + xt[2][8][32]
#define WS_STRIDE 33
#define WS_BUF (256 * WS_STRIDE)
#define XT_BUF (TPG * 32)
#define REP_SMEM ((2 * WS_BUF + 2 * XT_BUF) * 4)
#define NCH (HDIM / 32)      // 224 repair chunks

__device__ __half g_Whi[NEXP * HDIM];
__device__ __half g_Wlo[NEXP * HDIM];
__device__ float  g_scores[MAX_T * NEXP];
__device__ int    g_nflag;
__device__ int    g_flags[MAX_T];

typedef unsigned long long ull;

__device__ __forceinline__ ull pack2(float lo, float hi) {
    ull r; asm("mov.b64 %0, {%1, %2};" : "=l"(r) : "f"(lo), "f"(hi)); return r;
}
__device__ __forceinline__ void fma2_acc(ull& acc, ull a, ull b) {
    asm("fma.rn.f32x2 %0, %1, %2, %0;" : "+l"(acc) : "l"(a), "l"(b));
}
__device__ __forceinline__ ull fma2(ull a, ull b, ull c) {
    ull d; asm("fma.rn.f32x2 %0, %1, %2, %3;" : "=l"(d) : "l"(a), "l"(b), "l"(c)); return d;
}
__device__ __forceinline__ ull add2(ull a, ull b) {
    ull d; asm("add.rn.f32x2 %0, %1, %2;" : "=l"(d) : "l"(a), "l"(b)); return d;
}
__device__ __forceinline__ float2 unpk2(ull v) {
    float lo, hi; asm("mov.b64 {%0, %1}, %2;" : "=f"(lo), "=f"(hi) : "l"(v));
    return make_float2(lo, hi);
}

// ---------- K1: split W (x256) into fp16 hi/lo; reset flag counter ----------
__global__ void prep_kernel(const float* __restrict__ W) {
    if (blockIdx.x == 0 && threadIdx.x == 0) g_nflag = 0;
    const int total = NEXP * HDIM;
    for (int i = blockIdx.x * blockDim.x + threadIdx.x; i < total;
         i += gridDim.x * blockDim.x) {
        float ws = W[i] * 256.0f;
        __half h = __float2half_rn(ws);
        g_Whi[i] = h;
        g_Wlo[i] = __float2half_rn(ws - __half2float(h));
    }
}

// ---------- K2: wmma fp16 split-2 GEMM + bias + sigmoid ----------
__global__ __launch_bounds__(256, 1)
void gemm_kernel(const float* __restrict__ X, const float* __restrict__ bvec, int T)
{
    extern __shared__ __half sh[];
    const int tid = threadIdx.x;
    const int wid = tid >> 5;
    const int n0 = blockIdx.x * BN;
    const int m0 = blockIdx.y * BM;
    const int wm = wid & 3;
    const int wn = wid >> 2;

    wmma::fragment<wmma::accumulator, 16, 16, 16, float> acc[2][4];
#pragma unroll
    for (int mt = 0; mt < 2; ++mt)
#pragma unroll
        for (int nt = 0; nt < 4; ++nt) wmma::fill_fragment(acc[mt][nt], 0.0f);

    float4 av[4];
    uint4 bh[2], bl[2];

    auto gload = [&](int it) {
        const int kc = it * BK;
#pragma unroll
        for (int i = 0; i < 4; ++i) {
            const int idx = tid + 256 * i;
            const int row = idx >> 3, c4 = idx & 7;
            av[i] = __ldg((const float4*)(X + (size_t)(m0 + row) * HDIM + kc + c4 * 4));
        }
#pragma unroll
        for (int i = 0; i < 2; ++i) {
            const int idx = tid + 256 * i;
            const int row = idx >> 2, p = idx & 3;
            bh[i] = __ldg((const uint4*)(g_Whi + (size_t)(n0 + row) * HDIM + kc) + p);
            bl[i] = __ldg((const uint4*)(g_Wlo + (size_t)(n0 + row) * HDIM + kc) + p);
        }
    };

    auto fill = [&](int stage) {
        __half* Ahi = sh + stage * 4 * AR;
        __half* Alo = Ahi + AR;
        __half* Bhi = Alo + AR;
        __half* Blo = Bhi + AR;
#pragma unroll
        for (int i = 0; i < 4; ++i) {
            const int idx = tid + 256 * i;
            const int row = idx >> 3, c4 = idx & 7;
            float4 v = av[i];
            __half2 h01 = __floats2half2_rn(v.x, v.y);
            __half2 h23 = __floats2half2_rn(v.z, v.w);
            float2 f01 = __half22float2(h01), f23 = __half22float2(h23);
            __half2 l01 = __floats2half2_rn(v.x - f01.x, v.y - f01.y);
            __half2 l23 = __floats2half2_rn(v.z - f23.x, v.w - f23.y);
            uint2 ph, pl;
            ph.x = reinterpret_cast<unsigned&>(h01); ph.y = reinterpret_cast<unsigned&>(h23);
            pl.x = reinterpret_cast<unsigned&>(l01); pl.y = reinterpret_cast<unsigned&>(l23);
            *(uint2*)(Ahi + row * LDH + c4 * 4) = ph;
            *(uint2*)(Alo + row * LDH + c4 * 4) = pl;
        }
#pragma unroll
        for (int i = 0; i < 2; ++i) {
            const int idx = tid + 256 * i;
            const int row = idx >> 2, p = idx & 3;
            *(uint4*)(Bhi + row * LDH + p * 8) = bh[i];
            *(uint4*)(Blo + row * LDH + p * 8) = bl[i];
        }
    };

    gload(0);
    fill(0);
    __syncthreads();
    gload(1);

    for (int it = 0; it < NIT; ++it) {
        const int buf = it & 1;
        const __half* Ahi = sh + buf * 4 * AR;
        const __half* Alo = Ahi + AR;
        const __half* Bhi = Alo + AR;
        const __half* Blo = Bhi + AR;
#pragma unroll
        for (int kk = 0; kk < 2; ++kk) {
            wmma::fragment<wmma::matrix_a, 16, 16, 16, __half, wmma::row_major> ah[2], al[2];
#pragma unroll
            for (int mt = 0; mt < 2; ++mt) {
                const int r = wm * 32 + mt * 16;
                wmma::load_matrix_sync(ah[mt], Ahi + r * LDH + kk * 16, LDH);
                wmma::load_matrix_sync(al[mt], Alo + r * LDH + kk * 16, LDH);
            }
#pragma unroll
            for (int nt = 0; nt < 4; ++nt) {
                const int c = wn * 64 + nt * 16;
                wmma::fragment<wmma::matrix_b, 16, 16, 16, __half, wmma::col_major> fbh, fbl;
                wmma::load_matrix_sync(fbh, Bhi + c * LDH + kk * 16, LDH);
                wmma::load_matrix_sync(fbl, Blo + c * LDH + kk * 16, LDH);
#pragma unroll
                for (int mt = 0; mt < 2; ++mt) {
                    wmma::mma_sync(acc[mt][nt], ah[mt], fbh, acc[mt][nt]);
                    wmma::mma_sync(acc[mt][nt], ah[mt], fbl, acc[mt][nt]);
                    wmma::mma_sync(acc[mt][nt], al[mt], fbh, acc[mt][nt]);
                }
            }
        }
        if (it + 1 < NIT) {
            fill(buf ^ 1);               // regs hold tile it+1
            if (it + 2 < NIT) gload(it + 2);
        }
        __syncthreads();
    }

    float* sacc = (float*)sh;
#pragma unroll
    for (int mt = 0; mt < 2; ++mt)
#pragma unroll
        for (int nt = 0; nt < 4; ++nt)
            wmma::store_matrix_sync(sacc + (wm * 32 + mt * 16) * 128 + wn * 64 + nt * 16,
                                    acc[mt][nt], 128, wmma::mem_row_major);
    __syncthreads();
#pragma unroll
    for (int i = 0; i < 16; ++i) {
        const int idx = tid + 256 * i;
        const int row = idx >> 5, c4 = idx & 31;
        float4 v = *(float4*)(sacc + row * 128 + c4 * 4);
        const int n = n0 + c4 * 4;
        float4 o;
        o.x = 1.0f / (1.0f + expf(-(v.x * (1.0f/256.0f) + bvec[n])));
        o.y = 1.0f / (1.0f + expf(-(v.y * (1.0f/256.0f) + bvec[n+1])));
        o.z = 1.0f / (1.0f + expf(-(v.z * (1.0f/256.0f) + bvec[n+2])));
        o.w = 1.0f / (1.0f + expf(-(v.w * (1.0f/256.0f) + bvec[n+3])));
        *(float4*)(g_scores + (size_t)(m0 + row) * NEXP + n) = o;
    }
}

// ---------- warp-collective routing core ----------
__device__ __forceinline__ void route_token(const float* __restrict__ rs,
                                            const float* __restrict__ ebias,
                                            int lane, int t, int T,
                                            float* __restrict__ out, bool check)
{
    const float NEG_INF = -1e30f;
    float sfc[8];
#pragma unroll
    for (int i = 0; i < 8; ++i) sfc[i] = rs[i * 32 + lane] + ebias[i * 32 + lane];

    float gs[8];
#pragma unroll
    for (int i = 0; i < 8; ++i) {
        float m1 = sfc[i], m2 = NEG_INF;
#pragma unroll
        for (int off = 16; off > 0; off >>= 1) {
            float o1 = __shfl_xor_sync(0xffffffffu, m1, off);
            float o2 = __shfl_xor_sync(0xffffffffu, m2, off);
            float hi = fmaxf(m1, o1), lo = fminf(m1, o1);
            m1 = hi; m2 = fmaxf(fmaxf(m2, o2), lo);
        }
        gs[i] = m1 + m2;
    }

    unsigned gmask = 0, sel = 0;
    float g4 = 0.0f, g5 = 0.0f;
#pragma unroll
    for (int j = 0; j < 5; ++j) {
        float best = NEG_INF; int bg = 0;
#pragma unroll
        for (int g = 0; g < 8; ++g)
            if (!((sel >> g) & 1u) && gs[g] > best) { best = gs[g]; bg = g; }
        sel |= (1u << bg);
        if (j < 4) gmask |= (1u << bg);
        if (j == 3) g4 = best;
        if (j == 4) g5 = best;
    }

    float cv[8];
#pragma unroll
    for (int i = 0; i < 8; ++i) cv[i] = ((gmask >> i) & 1u) ? sfc[i] : 0.0f;

    unsigned used = 0;
    int idxs[8];
    float mmin = 1e30f, pv = 0.0f;
#pragma unroll
    for (int j = 0; j < 9; ++j) {
        float bv = NEG_INF; int be = 1 << 30;
#pragma unroll
        for (int i = 0; i < 8; ++i) {
            if (!((used >> i) & 1u)) {
                const float v = cv[i];
                const int e = i * 32 + lane;
                if (v > bv || (v == bv && e < be)) { bv = v; be = e; }
            }
        }
#pragma unroll
        for (int off = 16; off > 0; off >>= 1) {
            float ov = __shfl_xor_sync(0xffffffffu, bv, off);
            int oe = __shfl_xor_sync(0xffffffffu, be, off);
            if (ov > bv || (ov == bv && oe < be)) { bv = ov; be = oe; }
        }
        if (j < 8) idxs[j] = be;
        if ((be & 31) == lane) used |= (1u << (be >> 5));
        if (j > 0) mmin = fminf(mmin, pv - bv);
        pv = bv;
    }

    if (check && (mmin < TAU_E || (g4 - g5) < TAU_G)) {
        if (lane == 0) { int s = atomicAdd(&g_nflag, 1); g_flags[s] = t; }
    }

    float wj = 0.0f;
    if (lane < TOPK) wj = rs[idxs[lane]];
    float ssum = wj;
#pragma unroll
    for (int off = 4; off > 0; off >>= 1)
        ssum += __shfl_xor_sync(0xffffffffu, ssum, off);
    const float denom = ssum + 1e-20f;
    if (lane < TOPK) {
        out[(size_t)t * TOPK + lane] = (float)idxs[lane];
        out[(size_t)T * TOPK + (size_t)t * TOPK + lane] = wj / denom * SCALE_F;
    }
}

// ---------- K3: router ----------
__global__ __launch_bounds__(128)
void router_kernel(const float* __restrict__ ebias, float* __restrict__ out, int T)
{
    __shared__ float raw_s[4][NEXP];
    const int warp = threadIdx.x >> 5;
    const int lane = threadIdx.x & 31;
    const int t = blockIdx.x * 4 + warp;
    if (t >= T) return;
    float* rs = raw_s[warp];
#pragma unroll
    for (int i = 0; i < 2; ++i)
        *(float4*)(rs + i * 128 + lane * 4) =
            *(const float4*)(g_scores + (size_t)t * NEXP + i * 128 + lane * 4);
    __syncwarp();
    route_token(rs, ebias, lane, t, T, out, true);
}

// ---------- K4: exact repair, tiled mini-GEMM over flagged tokens ----------
__global__ __launch_bounds__(256)
void repair_kernel(const float* __restrict__ X, const float* __restrict__ W,
                   const float* __restrict__ bvec, const float* __restrict__ ebias,
                   float* __restrict__ out, int T)
{
    extern __shared__ float rsm[];
    float* ws = rsm;                         // [2][256][WS_STRIDE]
    float* xt = rsm + 2 * WS_BUF;            // [2][TPG][32]
    __shared__ float sc[TPG][NEXP];
    __shared__ int toks[TPG];

    const int tid = threadIdx.x;
    const int warp = tid >> 5, lane = tid & 31;
    const ull neg1 = pack2(-1.0f, -1.0f);
    const int nf = g_nflag;

    float4 wreg[8];
    float4 xreg;

    for (int grp = blockIdx.x; grp * TPG < nf; grp += gridDim.x) {
        const int cnt = min(TPG, nf - grp * TPG);
        if (tid < TPG) toks[tid] = g_flags[grp * TPG + min(tid, cnt - 1)];
        __syncthreads();

        auto wload = [&](int c) {
            const int kc = c * 32;
#pragma unroll
            for (int q = 0; q < 8; ++q) {
                const int f4 = tid + 256 * q;
                const int row = f4 >> 3, c4 = f4 & 7;
                wreg[q] = __ldg((const float4*)(W + (size_t)row * HDIM + kc + c4 * 4));
            }
            if (tid < TPG * 8) {
                const int j = tid >> 3, q = tid & 7;
                xreg = __ldg((const float4*)(X + (size_t)toks[j] * HDIM + kc + q * 4));
            }
        };
        auto sfill = [&](int stage) {
            float* wsb = ws + stage * WS_BUF;
#pragma unroll
            for (int q = 0; q < 8; ++q) {
                const int f4 = tid + 256 * q;
                const int row = f4 >> 3, c4 = f4 & 7;
                float* p = wsb + row * WS_STRIDE + c4 * 4;
                p[0] = wreg[q].x; p[1] = wreg[q].y; p[2] = wreg[q].z; p[3] = wreg[q].w;
            }
            if (tid < TPG * 8) {
                const int j = tid >> 3, q = tid & 7;
                *(float4*)(xt + stage * XT_BUF + j * 32 + q * 4) = xreg;
            }
        };

        ull alo[TPG], ahi[TPG], cmp[TPG];
#pragma unroll
        for (int j = 0; j < TPG; ++j) { alo[j] = 0; ahi[j] = 0; cmp[j] = 0; }

        wload(0);
        sfill(0);
        __syncthreads();
        wload(1);

        for (int c = 0; c < NCH; ++c) {
            const int buf = c & 1;
            const float* wrow = ws + buf * WS_BUF + tid * WS_STRIDE;
            const float* xb = xt + buf * XT_BUF;
#pragma unroll
            for (int u = 0; u < 16; ++u) {
                ull w2 = pack2(wrow[2 * u], wrow[2 * u + 1]);
#pragma unroll
                for (int j = 0; j < TPG; ++j) {
                    float2 xv = *(const float2*)(xb + j * 32 + 2 * u);
                    fma2_acc(alo[j], w2, pack2(xv.x, xv.y));
                }
            }
#pragma unroll
            for (int j = 0; j < TPG; ++j) {        // Kahan fold per 32-term chunk
                ull y = fma2(cmp[j], neg1, alo[j]);
                ull tt = add2(ahi[j], y);
                ull d = fma2(ahi[j], neg1, tt);
                cmp[j] = fma2(y, neg1, d);
                ahi[j] = tt;
                alo[j] = 0;
            }
            if (c + 1 < NCH) {
                sfill(buf ^ 1);                    // regs = chunk c+1
                if (c + 2 < NCH) wload(c + 2);
            }
            __syncthreads();
        }

        const float be = bvec[tid];
#pragma unroll
        for (int j = 0; j < TPG; ++j) {
            float2 v = unpk2(fma2(cmp[j], neg1, ahi[j]));
            float l = v.x + v.y + be;
            sc[j][tid] = 1.0f / (1.0f + expf(-l));
        }
        __syncthreads();
        if (warp < cnt) route_token(sc[warp], ebias, lane, toks[warp], T, out, false);
        __syncthreads();
    }
}

extern "C" void kernel_launch(void* const* d_in, const int* in_sizes, int n_in,
                              void* d_out, int out_size)
{
    const float* hs = (const float*)d_in[0];
    const float* W  = (const float*)d_in[1];
    const float* b  = (const float*)d_in[2];
    const float* eb = (const float*)d_in[3];
    const int T = in_sizes[0] / HDIM;

    cudaFuncSetAttribute(gemm_kernel, cudaFuncAttributeMaxDynamicSharedMemorySize, GEMM_SMEM);
    cudaFuncSetAttribute(repair_kernel, cudaFuncAttributeMaxDynamicSharedMemorySize, REP_SMEM);

    prep_kernel<<<256, 256>>>(W);
    dim3 ggrid(NEXP / BN, T / BM);
    gemm_kernel<<<ggrid, 256, GEMM_SMEM>>>(hs, b, T);
    router_kernel<<<(T + 3) / 4, 128>>>(eb, (float*)d_out, T);
    repair_kernel<<<256, 256, REP_SMEM>>>(hs, W, b, eb, (float*)d_out, T);
}